// round 1
// baseline (speedup 1.0000x reference)
#include <cuda_runtime.h>
#include <cuda_bf16.h>

// Problem constants
#define BATCH   16
#define SEQ     1024
#define DIM     640
#define HEADS   10
#define HDIM    64
#define QKVCOLS (3 * DIM)         // 1920
#define MROWS   (BATCH * SEQ)     // 16384
static __device__ __constant__ float SCALE_F = 0.03952847075210474f; // 640^-0.5

// Scratch (allocation is forbidden -> device globals)
// Layout [B, H, N, D] for Q,K,V; [B, N, DIM] for attention output.
__device__ float g_Q[BATCH * HEADS * SEQ * HDIM];
__device__ float g_K[BATCH * HEADS * SEQ * HDIM];
__device__ float g_V[BATCH * HEADS * SEQ * HDIM];
__device__ float g_AO[BATCH * SEQ * DIM];

// ---------------------------------------------------------------------------
// Kernel 1: QKV GEMM  C[16384,1920] = X[16384,640] @ W[640,1920] + b
// 64x64 block tile, BK=16, 256 threads, 4x4 micro-tile.
// Epilogue scatters into g_Q/g_K/g_V with [B,H,N,D] layout.
// ---------------------------------------------------------------------------
__global__ __launch_bounds__(256) void qkv_gemm_kernel(
    const float* __restrict__ X, const float* __restrict__ W,
    const float* __restrict__ bias)
{
    __shared__ float sA[16][65];  // [k][m], padded
    __shared__ float sB[16][65];  // [k][n], padded

    const int bn = blockIdx.x * 64;
    const int bm = blockIdx.y * 64;
    const int tid = threadIdx.x;
    const int tx = tid & 15;
    const int ty = tid >> 4;

    float acc[4][4];
#pragma unroll
    for (int i = 0; i < 4; i++)
#pragma unroll
        for (int j = 0; j < 4; j++) acc[i][j] = 0.f;

    for (int k0 = 0; k0 < DIM; k0 += 16) {
#pragma unroll
        for (int it = 0; it < 4; it++) {
            int idx = tid + it * 256;          // 0..1023
            int r = idx >> 4, c = idx & 15;    // A tile 64x16
            sA[c][r] = X[(bm + r) * DIM + k0 + c];
        }
#pragma unroll
        for (int it = 0; it < 4; it++) {
            int idx = tid + it * 256;
            int r = idx >> 6, c = idx & 63;    // B tile 16x64
            sB[r][c] = W[(k0 + r) * QKVCOLS + bn + c];
        }
        __syncthreads();
#pragma unroll
        for (int kk = 0; kk < 16; kk++) {
            float a[4], b[4];
#pragma unroll
            for (int i = 0; i < 4; i++) a[i] = sA[kk][4 * ty + i];
#pragma unroll
            for (int j = 0; j < 4; j++) b[j] = sB[kk][4 * tx + j];
#pragma unroll
            for (int i = 0; i < 4; i++)
#pragma unroll
                for (int j = 0; j < 4; j++) acc[i][j] += a[i] * b[j];
        }
        __syncthreads();
    }

    // Scatter epilogue
#pragma unroll
    for (int j = 0; j < 4; j++) {
        int c = bn + 4 * tx + j;
        int sel = c / DIM;
        int rem = c - sel * DIM;
        int h = rem >> 6;          // /64
        int d = rem & 63;
        float bv = bias[c];
        float* dst = (sel == 0) ? g_Q : (sel == 1) ? g_K : g_V;
#pragma unroll
        for (int i = 0; i < 4; i++) {
            int m = bm + 4 * ty + i;
            int b_ = m >> 10;       // /1024
            int n = m & 1023;
            dst[(((size_t)b_ * HEADS + h) * SEQ + n) * HDIM + d] = acc[i][j] + bv;
        }
    }
}

// ---------------------------------------------------------------------------
// Kernel 2: flash attention. One block = (bh, 64-query tile).
// 256 threads. K/V streamed in 32-row tiles. Online softmax.
// smem: sQ 64x65 + sK 32x65 + sV 32x65 + sP 64x33 = 41,728 B (static)
// ---------------------------------------------------------------------------
__global__ __launch_bounds__(256) void attn_kernel()
{
    __shared__ float sQ[64][65];
    __shared__ float sK[32][65];
    __shared__ float sV[32][65];
    __shared__ float sP[64][33];

    const int bh = blockIdx.x;      // 0..159
    const int qt = blockIdx.y;      // 0..15
    const int b  = bh / HEADS;
    const int h  = bh - b * HEADS;

    const float* Qg = g_Q + (size_t)bh * SEQ * HDIM + qt * 64 * HDIM;
    const float* Kg = g_K + (size_t)bh * SEQ * HDIM;
    const float* Vg = g_V + (size_t)bh * SEQ * HDIM;

    const int tid = threadIdx.x;
    const int tx = tid & 15;
    const int ty = tid >> 4;

    // Load Q tile (64x64)
    for (int i = tid; i < 64 * 64; i += 256) sQ[i >> 6][i & 63] = Qg[i];

    float accO[4][4];
    float mrow[4], lrow[4];
#pragma unroll
    for (int i = 0; i < 4; i++) {
        mrow[i] = -1e30f; lrow[i] = 0.f;
#pragma unroll
        for (int j = 0; j < 4; j++) accO[i][j] = 0.f;
    }
    __syncthreads();

    for (int jt = 0; jt < SEQ / 32; jt++) {
        const float* Kt = Kg + jt * 32 * HDIM;
        const float* Vt = Vg + jt * 32 * HDIM;
        for (int i = tid; i < 32 * 64; i += 256) {
            sK[i >> 6][i & 63] = Kt[i];
            sV[i >> 6][i & 63] = Vt[i];
        }
        __syncthreads();

        // S = scale * Q K^T : thread computes rows 4ty+i (4), cols 2tx+j (2)
        float s[4][2];
#pragma unroll
        for (int i = 0; i < 4; i++)
#pragma unroll
            for (int j = 0; j < 2; j++) s[i][j] = 0.f;
#pragma unroll
        for (int k = 0; k < 64; k++) {
            float a[4], kb[2];
#pragma unroll
            for (int i = 0; i < 4; i++) a[i] = sQ[4 * ty + i][k];
#pragma unroll
            for (int j = 0; j < 2; j++) kb[j] = sK[2 * tx + j][k];
#pragma unroll
            for (int i = 0; i < 4; i++)
#pragma unroll
                for (int j = 0; j < 2; j++) s[i][j] += a[i] * kb[j];
        }

        // online softmax per row (reduce across the 16 tx lanes)
#pragma unroll
        for (int i = 0; i < 4; i++) {
            float sc0 = s[i][0] * SCALE_F;
            float sc1 = s[i][1] * SCALE_F;
            float mx = fmaxf(sc0, sc1);
#pragma unroll
            for (int off = 1; off < 16; off <<= 1)
                mx = fmaxf(mx, __shfl_xor_sync(0xffffffffu, mx, off));
            float Mnew = fmaxf(mrow[i], mx);
            float corr = __expf(mrow[i] - Mnew);
            float p0 = __expf(sc0 - Mnew);
            float p1 = __expf(sc1 - Mnew);
            float psum = p0 + p1;
#pragma unroll
            for (int off = 1; off < 16; off <<= 1)
                psum += __shfl_xor_sync(0xffffffffu, psum, off);
            lrow[i] = lrow[i] * corr + psum;
            mrow[i] = Mnew;
#pragma unroll
            for (int j = 0; j < 4; j++) accO[i][j] *= corr;
            sP[4 * ty + i][2 * tx + 0] = p0;
            sP[4 * ty + i][2 * tx + 1] = p1;
        }
        __syncthreads();

        // O += P V : thread owns rows 4ty+i, d-cols 4tx+j
#pragma unroll
        for (int k = 0; k < 32; k++) {
            float p[4], v[4];
#pragma unroll
            for (int i = 0; i < 4; i++) p[i] = sP[4 * ty + i][k];
#pragma unroll
            for (int j = 0; j < 4; j++) v[j] = sV[k][4 * tx + j];
#pragma unroll
            for (int i = 0; i < 4; i++)
#pragma unroll
                for (int j = 0; j < 4; j++) accO[i][j] += p[i] * v[j];
        }
        __syncthreads();
    }

    // Write to g_AO [B, N, H*64 + d]
#pragma unroll
    for (int i = 0; i < 4; i++) {
        int n = qt * 64 + 4 * ty + i;
        float inv = 1.f / lrow[i];
        size_t base = ((size_t)b * SEQ + n) * DIM + h * HDIM + 4 * tx;
#pragma unroll
        for (int j = 0; j < 4; j++)
            g_AO[base + j] = accO[i][j] * inv;
    }
}

// ---------------------------------------------------------------------------
// Kernel 3: output projection  out[16384,640] = AO @ Wout + bout
// ---------------------------------------------------------------------------
__global__ __launch_bounds__(256) void out_gemm_kernel(
    const float* __restrict__ W, const float* __restrict__ bias,
    float* __restrict__ out)
{
    __shared__ float sA[16][65];
    __shared__ float sB[16][65];

    const int bn = blockIdx.x * 64;
    const int bm = blockIdx.y * 64;
    const int tid = threadIdx.x;
    const int tx = tid & 15;
    const int ty = tid >> 4;

    float acc[4][4];
#pragma unroll
    for (int i = 0; i < 4; i++)
#pragma unroll
        for (int j = 0; j < 4; j++) acc[i][j] = 0.f;

    for (int k0 = 0; k0 < DIM; k0 += 16) {
#pragma unroll
        for (int it = 0; it < 4; it++) {
            int idx = tid + it * 256;
            int r = idx >> 4, c = idx & 15;
            sA[c][r] = g_AO[(size_t)(bm + r) * DIM + k0 + c];
        }
#pragma unroll
        for (int it = 0; it < 4; it++) {
            int idx = tid + it * 256;
            int r = idx >> 6, c = idx & 63;
            sB[r][c] = W[(k0 + r) * DIM + bn + c];
        }
        __syncthreads();
#pragma unroll
        for (int kk = 0; kk < 16; kk++) {
            float a[4], b[4];
#pragma unroll
            for (int i = 0; i < 4; i++) a[i] = sA[kk][4 * ty + i];
#pragma unroll
            for (int j = 0; j < 4; j++) b[j] = sB[kk][4 * tx + j];
#pragma unroll
            for (int i = 0; i < 4; i++)
#pragma unroll
                for (int j = 0; j < 4; j++) acc[i][j] += a[i] * b[j];
        }
        __syncthreads();
    }

#pragma unroll
    for (int i = 0; i < 4; i++) {
        int m = bm + 4 * ty + i;
#pragma unroll
        for (int j = 0; j < 4; j++) {
            int c = bn + 4 * tx + j;
            out[(size_t)m * DIM + c] = acc[i][j] + bias[c];
        }
    }
}

// ---------------------------------------------------------------------------
extern "C" void kernel_launch(void* const* d_in, const int* in_sizes, int n_in,
                              void* d_out, int out_size)
{
    const float* x     = (const float*)d_in[0];
    const float* w_qkv = (const float*)d_in[1];
    const float* b_qkv = (const float*)d_in[2];
    const float* w_out = (const float*)d_in[3];
    const float* b_out = (const float*)d_in[4];
    float* out = (float*)d_out;

    qkv_gemm_kernel<<<dim3(QKVCOLS / 64, MROWS / 64), 256>>>(x, w_qkv, b_qkv);
    attn_kernel<<<dim3(BATCH * HEADS, SEQ / 64), 256>>>();
    out_gemm_kernel<<<dim3(DIM / 64, MROWS / 64), 256>>>(w_out, b_out, out);
}

// round 6
// speedup vs baseline: 7.5473x; 7.5473x over previous
#include <cuda_runtime.h>
#include <cuda_fp16.h>
#include <cstdint>

// ---------------------------------------------------------------------------
// Problem constants
// ---------------------------------------------------------------------------
#define BATCH   16
#define SEQ     1024
#define DIM     640
#define HEADS   10
#define HDIM    64
#define QKVCOLS 1920
#define MROWS   16384
#define BH      160
#define SCALE_F 0.03952847075210474f   // 640^-0.5

// ---------------------------------------------------------------------------
// Device scratch (allocation forbidden -> device globals)
// ---------------------------------------------------------------------------
__device__ __half g_X [MROWS * DIM];        // x as fp16            [m][k]
__device__ __half g_Wq[QKVCOLS * DIM];      // w_qkv^T fp16         [n][k]
__device__ __half g_Wo[DIM * DIM];          // w_out^T fp16         [n][k]
__device__ __half g_Q [BH * SEQ * HDIM];    // (pre-scaled) Q       [bh][n][d]
__device__ __half g_K [BH * SEQ * HDIM];    // K                    [bh][n][d]
__device__ __half g_Vt[BH * HDIM * SEQ];    // V transposed         [bh][d][n]
__device__ __half g_AO[MROWS * DIM];        // attention output     [m][dim]

// ---------------------------------------------------------------------------
// PTX helpers (baseline sm_80+ instructions only -- compile for plain sm_103)
// ---------------------------------------------------------------------------
__device__ __forceinline__ uint32_t smem_u32(const void* p) {
    uint32_t a;
    asm("{ .reg .u64 t; cvta.to.shared.u64 t, %1; cvt.u32.u64 %0, t; }" : "=r"(a) : "l"(p));
    return a;
}
__device__ __forceinline__ void ldm_x4(uint32_t* r, uint32_t addr) {
    asm volatile("ldmatrix.sync.aligned.m8n8.x4.shared.b16 {%0,%1,%2,%3}, [%4];"
                 : "=r"(r[0]), "=r"(r[1]), "=r"(r[2]), "=r"(r[3]) : "r"(addr));
}
__device__ __forceinline__ void mma_16816(float* c, const uint32_t* a, const uint32_t* b) {
    asm volatile("mma.sync.aligned.m16n8k16.row.col.f32.f16.f16.f32 "
                 "{%0,%1,%2,%3},{%4,%5,%6,%7},{%8,%9},{%0,%1,%2,%3};"
                 : "+f"(c[0]), "+f"(c[1]), "+f"(c[2]), "+f"(c[3])
                 : "r"(a[0]), "r"(a[1]), "r"(a[2]), "r"(a[3]), "r"(b[0]), "r"(b[1]));
}
__device__ __forceinline__ void cp16(uint32_t dst, const void* src) {
    asm volatile("cp.async.cg.shared.global [%0], [%1], 16;" :: "r"(dst), "l"(src));
}
#define CP_COMMIT() asm volatile("cp.async.commit_group;" ::: "memory")
#define CP_WAIT0()  asm volatile("cp.async.wait_group 0;" ::: "memory")
#define CP_WAIT1()  asm volatile("cp.async.wait_group 1;" ::: "memory")

__device__ __forceinline__ uint32_t packh2(float a, float b) {
    __half2 h = __floats2half2_rn(a, b);
    return *reinterpret_cast<uint32_t*>(&h);
}

// ---------------------------------------------------------------------------
// Convert kernels
// ---------------------------------------------------------------------------
__global__ void convert_x_kernel(const float* __restrict__ x, int n8) {
    int i = blockIdx.x * blockDim.x + threadIdx.x;
    if (i >= n8) return;
    const float4* p = reinterpret_cast<const float4*>(x) + (size_t)i * 2;
    float4 a = p[0], b = p[1];
    uint4 o;
    o.x = packh2(a.x, a.y); o.y = packh2(a.z, a.w);
    o.z = packh2(b.x, b.y); o.w = packh2(b.z, b.w);
    reinterpret_cast<uint4*>(g_X)[i] = o;
}

// in[K][N] fp32  ->  out[N][K] fp16
__global__ void transpose_h_kernel(const float* __restrict__ in, __half* __restrict__ out,
                                   int K, int N) {
    __shared__ float s[32][33];
    int n0 = blockIdx.x * 32, k0 = blockIdx.y * 32;
    int tx = threadIdx.x, ty = threadIdx.y;
#pragma unroll
    for (int i = 0; i < 4; i++)
        s[ty + i * 8][tx] = in[(size_t)(k0 + ty + i * 8) * N + n0 + tx];
    __syncthreads();
#pragma unroll
    for (int i = 0; i < 4; i++) {
        int r = ty + i * 8;
        out[(size_t)(n0 + r) * K + k0 + tx] = __float2half_rn(s[tx][r]);
    }
}

// ---------------------------------------------------------------------------
// Shared GEMM mainloop: C[128x128] = A[128x640] * B[128x640]^T
// 256 threads, 8 warps as 4(m) x 2(n); warp tile 32x64.
// smem rows padded to 40 halves (80B) -> conflict-free ldmatrix.
// ---------------------------------------------------------------------------
#define GST 5120   // halves per stage buffer (128*40)

__device__ __forceinline__ void gemm_mainloop(const __half* __restrict__ Ag,
                                              const __half* __restrict__ Bg,
                                              __half* sm, float acc[2][8][4]) {
    const int tid  = threadIdx.x;
    const int lane = tid & 31, wid = tid >> 5;
    const int wm = wid >> 1, wn = wid & 1;
    const int ldr = (lane & 7) + ((lane >> 3) & 1) * 8;
    const int hib = (lane >> 4) * 16;
    const uint32_t base = smem_u32(sm);
    const uint32_t sA[2] = { base,            base + 4 * GST };
    const uint32_t sB[2] = { base + 2 * GST,  base + 6 * GST };   // byte offsets

    auto load_stage = [&](int it, int buf) {
        const int k0 = it * 32;
        for (int i = tid; i < 512; i += 256) {
            int r = i >> 2, c = i & 3;
            uint32_t so = (uint32_t)(r * 40 + c * 8) * 2;
            cp16(sA[buf] + so, Ag + (size_t)r * DIM + k0 + c * 8);
            cp16(sB[buf] + so, Bg + (size_t)r * DIM + k0 + c * 8);
        }
        CP_COMMIT();
    };

    load_stage(0, 0);
    for (int it = 0; it < 20; ++it) {
        const int buf = it & 1;
        if (it < 19) { load_stage(it + 1, buf ^ 1); CP_WAIT1(); }
        else         { CP_WAIT0(); }
        __syncthreads();
#pragma unroll
        for (int kb = 0; kb < 2; ++kb) {
            uint32_t af[2][4], bf[8][2];
#pragma unroll
            for (int mt = 0; mt < 2; ++mt)
                ldm_x4(af[mt], sA[buf] + (uint32_t)((wm * 32 + mt * 16 + ldr) * 40) * 2 + kb * 32 + hib);
#pragma unroll
            for (int np = 0; np < 4; ++np) {
                uint32_t r[4];
                ldm_x4(r, sB[buf] + (uint32_t)((wn * 64 + np * 16 + ldr) * 40) * 2 + kb * 32 + hib);
                bf[np * 2][0] = r[0]; bf[np * 2][1] = r[2];
                bf[np * 2 + 1][0] = r[1]; bf[np * 2 + 1][1] = r[3];
            }
#pragma unroll
            for (int mt = 0; mt < 2; ++mt)
#pragma unroll
                for (int nt = 0; nt < 8; ++nt)
                    mma_16816(acc[mt][nt], af[mt], bf[nt]);
        }
        __syncthreads();
    }
}

// ---------------------------------------------------------------------------
// QKV GEMM + scatter epilogue. grid (15, 128), 256 threads.
// ---------------------------------------------------------------------------
__global__ __launch_bounds__(256) void qkv_mma_kernel(const float* __restrict__ bias) {
    __shared__ __half sm[8 * GST / 2];   // 20480 halves = 40KB
    float acc[2][8][4];
#pragma unroll
    for (int i = 0; i < 2; i++)
#pragma unroll
        for (int j = 0; j < 8; j++)
#pragma unroll
            for (int q = 0; q < 4; q++) acc[i][j][q] = 0.f;

    const int bn = blockIdx.x * 128, bm = blockIdx.y * 128;
    gemm_mainloop(g_X + (size_t)bm * DIM, g_Wq + (size_t)bn * DIM, sm, acc);

    const int tid = threadIdx.x, lane = tid & 31, wid = tid >> 5;
    const int wm = wid >> 1, wn = wid & 1;
    const int gid = lane >> 2, tig = lane & 3;
    const int sel = bn / DIM;                  // 0=Q 1=K 2=V
    const int cc  = bn - sel * DIM;
    const int h0  = cc >> 6;
    const int b   = bm >> 10, n0 = bm & 1023;

    if (sel < 2) {
        __half* dst = sel ? g_K : g_Q;
        const float sc = sel ? 1.f : SCALE_F;
#pragma unroll
        for (int mt = 0; mt < 2; ++mt)
#pragma unroll
            for (int nt = 0; nt < 8; ++nt) {
                int ct = wn * 64 + nt * 8 + 2 * tig;
                int h = h0 + wn, d = ct & 63;
                float b0 = bias[bn + ct], b1 = bias[bn + ct + 1];
                int r0 = wm * 32 + mt * 16 + gid;
                size_t base = (((size_t)b * HEADS + h) * SEQ + n0 + r0) * HDIM + d;
                *(__half2*)(dst + base) =
                    __floats2half2_rn((acc[mt][nt][0] + b0) * sc, (acc[mt][nt][1] + b1) * sc);
                *(__half2*)(dst + base + (size_t)8 * HDIM) =
                    __floats2half2_rn((acc[mt][nt][2] + b0) * sc, (acc[mt][nt][3] + b1) * sc);
            }
    } else {
        // V: transpose through smem to [bh][d][n]
        __syncthreads();
        __half* sT = sm;   // [128 cols][136]
#pragma unroll
        for (int mt = 0; mt < 2; ++mt)
#pragma unroll
            for (int nt = 0; nt < 8; ++nt) {
                int ct = wn * 64 + nt * 8 + 2 * tig;
                int r0 = wm * 32 + mt * 16 + gid;
                float b0 = bias[bn + ct], b1 = bias[bn + ct + 1];
                sT[ct * 136 + r0]           = __float2half_rn(acc[mt][nt][0] + b0);
                sT[(ct + 1) * 136 + r0]     = __float2half_rn(acc[mt][nt][1] + b1);
                sT[ct * 136 + r0 + 8]       = __float2half_rn(acc[mt][nt][2] + b0);
                sT[(ct + 1) * 136 + r0 + 8] = __float2half_rn(acc[mt][nt][3] + b1);
            }
        __syncthreads();
        int row = tid >> 1, part = tid & 1;           // row = tile col (head-dim)
        int h = h0 + (row >> 6), d = row & 63;
        __half* dst = g_Vt + (((size_t)b * HEADS + h) * HDIM + d) * SEQ + n0 + part * 64;
        const uint4* s4 = (const uint4*)(sT + row * 136 + part * 64);
#pragma unroll
        for (int q = 0; q < 8; ++q) ((uint4*)dst)[q] = s4[q];
    }
}

// ---------------------------------------------------------------------------
// Output projection. grid (5, 128), 256 threads.
// ---------------------------------------------------------------------------
__global__ __launch_bounds__(256) void proj_mma_kernel(const float* __restrict__ bias,
                                                       float* __restrict__ out) {
    __shared__ __half sm[8 * GST / 2];
    float acc[2][8][4];
#pragma unroll
    for (int i = 0; i < 2; i++)
#pragma unroll
        for (int j = 0; j < 8; j++)
#pragma unroll
            for (int q = 0; q < 4; q++) acc[i][j][q] = 0.f;

    const int bn = blockIdx.x * 128, bm = blockIdx.y * 128;
    gemm_mainloop(g_AO + (size_t)bm * DIM, g_Wo + (size_t)bn * DIM, sm, acc);

    const int tid = threadIdx.x, lane = tid & 31, wid = tid >> 5;
    const int wm = wid >> 1, wn = wid & 1;
    const int gid = lane >> 2, tig = lane & 3;
#pragma unroll
    for (int mt = 0; mt < 2; ++mt)
#pragma unroll
        for (int nt = 0; nt < 8; ++nt) {
            int ct = wn * 64 + nt * 8 + 2 * tig;
            int m0 = bm + wm * 32 + mt * 16 + gid;
            float b0 = bias[bn + ct], b1 = bias[bn + ct + 1];
            float2 v0 = make_float2(acc[mt][nt][0] + b0, acc[mt][nt][1] + b1);
            float2 v1 = make_float2(acc[mt][nt][2] + b0, acc[mt][nt][3] + b1);
            *(float2*)(out + (size_t)m0 * DIM + bn + ct) = v0;
            *(float2*)(out + (size_t)(m0 + 8) * DIM + bn + ct) = v1;
        }
}

// ---------------------------------------------------------------------------
// Flash attention. grid (160, 8), 256 threads = 8 warps, each warp owns 16
// query rows x all 64 keys -> softmax rows and P stay in registers.
// smem: Q[128][72] + 2x K[64][72] + 2x V[64][72]  (55296B dynamic)
// ---------------------------------------------------------------------------
#define ASM_Q  0
#define ASM_K0 9216
#define ASM_K1 13824
#define ASM_V0 18432
#define ASM_V1 23040
#define ASM_BYTES (27648 * 2)

__global__ __launch_bounds__(256) void attn_mma_kernel() {
    extern __shared__ __half dsm[];
    const int tid = threadIdx.x, lane = tid & 31, wid = tid >> 5;
    const int gid = lane >> 2, tig = lane & 3;
    const int bh = blockIdx.x, bq = blockIdx.y * 128;
    const int b = bh / HEADS, h = bh - b * HEADS;
    const int ldr = (lane & 7) + ((lane >> 3) & 1) * 8;
    const int hib = (lane >> 4) * 16;

    const __half* Qg = g_Q + ((size_t)bh * SEQ + bq) * HDIM;
    const __half* Kg = g_K + (size_t)bh * SEQ * HDIM;
    const __half* Vg = g_Vt + (size_t)bh * HDIM * SEQ;

    // Q tile (resident, padded 72-half rows)
    for (int i = tid; i < 1024; i += 256) {
        int r = i >> 3, c = i & 7;
        *(uint4*)(dsm + ASM_Q + r * 72 + c * 8) = *(const uint4*)(Qg + (size_t)r * HDIM + c * 8);
    }
    __syncthreads();

    uint32_t qf[4][4];
    {
        uint32_t qb = smem_u32(dsm + ASM_Q);
#pragma unroll
        for (int kb = 0; kb < 4; ++kb)
            ldm_x4(qf[kb], qb + (uint32_t)((wid * 16 + ldr) * 72) * 2 + kb * 32 + hib);
    }
    const uint32_t kS[2] = { smem_u32(dsm + ASM_K0), smem_u32(dsm + ASM_K1) };
    const uint32_t vS[2] = { smem_u32(dsm + ASM_V0), smem_u32(dsm + ASM_V1) };

    auto load_kv = [&](int jt, int buf) {
        const __half* Ks = Kg + (size_t)jt * 64 * HDIM;
        const __half* Vs = Vg + jt * 64;
        for (int i = tid; i < 512; i += 256) {
            int r = i >> 3, c = i & 7;
            uint32_t so = (uint32_t)(r * 72 + c * 8) * 2;
            cp16(kS[buf] + so, Ks + (size_t)r * HDIM + c * 8);
            cp16(vS[buf] + so, Vs + (size_t)r * SEQ + c * 8);
        }
        CP_COMMIT();
    };

    float mrow[2] = {-1e30f, -1e30f}, lrow[2] = {0.f, 0.f};
    float oacc[8][4];
#pragma unroll
    for (int j = 0; j < 8; j++)
#pragma unroll
        for (int q = 0; q < 4; q++) oacc[j][q] = 0.f;

    load_kv(0, 0);
    for (int jt = 0; jt < 16; ++jt) {
        const int buf = jt & 1;
        if (jt < 15) { load_kv(jt + 1, buf ^ 1); CP_WAIT1(); }
        else         { CP_WAIT0(); }
        __syncthreads();

        // S = Q K^T  (warp: 16 rows x 64 keys), Q pre-scaled
        float sacc[8][4];
#pragma unroll
        for (int j = 0; j < 8; j++)
#pragma unroll
            for (int q = 0; q < 4; q++) sacc[j][q] = 0.f;
#pragma unroll
        for (int kb = 0; kb < 4; ++kb) {
            uint32_t bf[8][2];
#pragma unroll
            for (int np = 0; np < 4; ++np) {
                uint32_t r[4];
                ldm_x4(r, kS[buf] + (uint32_t)((np * 16 + ldr) * 72) * 2 + kb * 32 + hib);
                bf[np * 2][0] = r[0]; bf[np * 2][1] = r[2];
                bf[np * 2 + 1][0] = r[1]; bf[np * 2 + 1][1] = r[3];
            }
#pragma unroll
            for (int nt = 0; nt < 8; ++nt) mma_16816(sacc[nt], qf[kb], bf[nt]);
        }

        // online softmax over 2 rows/thread (quad-replicated)
        float mx0 = -1e30f, mx1 = -1e30f;
#pragma unroll
        for (int nt = 0; nt < 8; ++nt) {
            mx0 = fmaxf(mx0, fmaxf(sacc[nt][0], sacc[nt][1]));
            mx1 = fmaxf(mx1, fmaxf(sacc[nt][2], sacc[nt][3]));
        }
        mx0 = fmaxf(mx0, __shfl_xor_sync(0xffffffffu, mx0, 1));
        mx0 = fmaxf(mx0, __shfl_xor_sync(0xffffffffu, mx0, 2));
        mx1 = fmaxf(mx1, __shfl_xor_sync(0xffffffffu, mx1, 1));
        mx1 = fmaxf(mx1, __shfl_xor_sync(0xffffffffu, mx1, 2));
        float Mn0 = fmaxf(mrow[0], mx0), Mn1 = fmaxf(mrow[1], mx1);
        float c0 = __expf(mrow[0] - Mn0), c1 = __expf(mrow[1] - Mn1);
        mrow[0] = Mn0; mrow[1] = Mn1;
        float s0 = 0.f, s1 = 0.f;
#pragma unroll
        for (int nt = 0; nt < 8; ++nt) {
            float p00 = __expf(sacc[nt][0] - Mn0), p01 = __expf(sacc[nt][1] - Mn0);
            float p10 = __expf(sacc[nt][2] - Mn1), p11 = __expf(sacc[nt][3] - Mn1);
            sacc[nt][0] = p00; sacc[nt][1] = p01; sacc[nt][2] = p10; sacc[nt][3] = p11;
            s0 += p00 + p01; s1 += p10 + p11;
        }
        s0 += __shfl_xor_sync(0xffffffffu, s0, 1);
        s0 += __shfl_xor_sync(0xffffffffu, s0, 2);
        s1 += __shfl_xor_sync(0xffffffffu, s1, 1);
        s1 += __shfl_xor_sync(0xffffffffu, s1, 2);
        lrow[0] = lrow[0] * c0 + s0;
        lrow[1] = lrow[1] * c1 + s1;
#pragma unroll
        for (int nt = 0; nt < 8; ++nt) {
            oacc[nt][0] *= c0; oacc[nt][1] *= c0;
            oacc[nt][2] *= c1; oacc[nt][3] *= c1;
        }

        // O += P V  : P fragments packed straight from registers
#pragma unroll
        for (int kb = 0; kb < 4; ++kb) {
            uint32_t pa[4] = {
                packh2(sacc[2 * kb][0],     sacc[2 * kb][1]),
                packh2(sacc[2 * kb][2],     sacc[2 * kb][3]),
                packh2(sacc[2 * kb + 1][0], sacc[2 * kb + 1][1]),
                packh2(sacc[2 * kb + 1][2], sacc[2 * kb + 1][3]) };
            uint32_t vf[8][2];
#pragma unroll
            for (int np = 0; np < 4; ++np) {
                uint32_t r[4];
                ldm_x4(r, vS[buf] + (uint32_t)((np * 16 + ldr) * 72) * 2 + kb * 32 + hib);
                vf[np * 2][0] = r[0]; vf[np * 2][1] = r[2];
                vf[np * 2 + 1][0] = r[1]; vf[np * 2 + 1][1] = r[3];
            }
#pragma unroll
            for (int nt = 0; nt < 8; ++nt) mma_16816(oacc[nt], pa, vf[nt]);
        }
        __syncthreads();
    }

    // epilogue -> AO fp16
    float inv0 = 1.f / lrow[0], inv1 = 1.f / lrow[1];
    size_t m0 = (size_t)b * SEQ + bq + wid * 16 + gid;
#pragma unroll
    for (int nt = 0; nt < 8; ++nt) {
        int col = h * HDIM + nt * 8 + 2 * tig;
        *(__half2*)(g_AO + m0 * DIM + col) =
            __floats2half2_rn(oacc[nt][0] * inv0, oacc[nt][1] * inv0);
        *(__half2*)(g_AO + (m0 + 8) * DIM + col) =
            __floats2half2_rn(oacc[nt][2] * inv1, oacc[nt][3] * inv1);
    }
}

// ---------------------------------------------------------------------------
extern "C" void kernel_launch(void* const* d_in, const int* in_sizes, int n_in,
                              void* d_out, int out_size)
{
    const float* x     = (const float*)d_in[0];
    const float* w_qkv = (const float*)d_in[1];
    const float* b_qkv = (const float*)d_in[2];
    const float* w_out = (const float*)d_in[3];
    const float* b_out = (const float*)d_in[4];
    float* out = (float*)d_out;

    static int attr_set = 0;
    if (!attr_set) {
        cudaFuncSetAttribute(attn_mma_kernel, cudaFuncAttributeMaxDynamicSharedMemorySize, ASM_BYTES);
        attr_set = 1;
    }

    __half *wq, *wo;
    cudaGetSymbolAddress((void**)&wq, g_Wq);
    cudaGetSymbolAddress((void**)&wo, g_Wo);

    // converts
    convert_x_kernel<<<(MROWS * DIM / 8 + 255) / 256, 256>>>(x, MROWS * DIM / 8);
    transpose_h_kernel<<<dim3(QKVCOLS / 32, DIM / 32), dim3(32, 8)>>>(w_qkv, wq, DIM, QKVCOLS);
    transpose_h_kernel<<<dim3(DIM / 32, DIM / 32), dim3(32, 8)>>>(w_out, wo, DIM, DIM);
    // QKV GEMM
    qkv_mma_kernel<<<dim3(QKVCOLS / 128, MROWS / 128), 256>>>(b_qkv);
    // attention
    attn_mma_kernel<<<dim3(BH, SEQ / 128), 256, ASM_BYTES>>>();
    // output projection
    proj_mma_kernel<<<dim3(DIM / 128, MROWS / 128), 256>>>(b_out, out);
}

// round 8
// speedup vs baseline: 7.6092x; 1.0082x over previous
#include <cuda_runtime.h>
#include <cuda_fp16.h>
#include <cstdint>

// ---------------------------------------------------------------------------
// Problem constants
// ---------------------------------------------------------------------------
#define BATCH   16
#define SEQ     1024
#define DIM     640
#define HEADS   10
#define HDIM    64
#define QKVCOLS 1920
#define MROWS   16384
#define BH      160
#define SCALE_F 0.03952847075210474f   // 640^-0.5

// ---------------------------------------------------------------------------
// Device scratch (allocation forbidden -> device globals)
// ---------------------------------------------------------------------------
__device__ __half g_X [MROWS * DIM];        // x as fp16            [m][k]
__device__ __half g_Wq[QKVCOLS * DIM];      // w_qkv^T fp16         [n][k]
__device__ __half g_Wo[DIM * DIM];          // w_out^T fp16         [n][k]
__device__ __half g_Q [BH * SEQ * HDIM];    // (pre-scaled) Q       [bh][n][d]
__device__ __half g_K [BH * SEQ * HDIM];    // K                    [bh][n][d]
__device__ __half g_Vt[BH * HDIM * SEQ];    // V transposed         [bh][d][n]
__device__ __half g_AO[MROWS * DIM];        // attention output     [m][dim]

// ---------------------------------------------------------------------------
// PTX helpers (baseline sm_80+ instructions only -- compile for plain sm_103)
// ---------------------------------------------------------------------------
__device__ __forceinline__ uint32_t smem_u32(const void* p) {
    uint32_t a;
    asm("{ .reg .u64 t; cvta.to.shared.u64 t, %1; cvt.u32.u64 %0, t; }" : "=r"(a) : "l"(p));
    return a;
}
__device__ __forceinline__ void ldm_x4(uint32_t* r, uint32_t addr) {
    asm volatile("ldmatrix.sync.aligned.m8n8.x4.shared.b16 {%0,%1,%2,%3}, [%4];"
                 : "=r"(r[0]), "=r"(r[1]), "=r"(r[2]), "=r"(r[3]) : "r"(addr));
}
__device__ __forceinline__ void mma_16816(float* c, const uint32_t* a, const uint32_t* b) {
    asm volatile("mma.sync.aligned.m16n8k16.row.col.f32.f16.f16.f32 "
                 "{%0,%1,%2,%3},{%4,%5,%6,%7},{%8,%9},{%0,%1,%2,%3};"
                 : "+f"(c[0]), "+f"(c[1]), "+f"(c[2]), "+f"(c[3])
                 : "r"(a[0]), "r"(a[1]), "r"(a[2]), "r"(a[3]), "r"(b[0]), "r"(b[1]));
}
__device__ __forceinline__ void cp16(uint32_t dst, const void* src) {
    asm volatile("cp.async.cg.shared.global [%0], [%1], 16;" :: "r"(dst), "l"(src));
}
#define CP_COMMIT() asm volatile("cp.async.commit_group;" ::: "memory")
#define CP_WAIT0()  asm volatile("cp.async.wait_group 0;" ::: "memory")
#define CP_WAIT1()  asm volatile("cp.async.wait_group 1;" ::: "memory")
#define CP_WAIT2()  asm volatile("cp.async.wait_group 2;" ::: "memory")

__device__ __forceinline__ uint32_t packh2(float a, float b) {
    __half2 h = __floats2half2_rn(a, b);
    return *reinterpret_cast<uint32_t*>(&h);
}

// ---------------------------------------------------------------------------
// Convert kernels
// ---------------------------------------------------------------------------
__global__ void convert_x_kernel(const float* __restrict__ x, int n8) {
    int i = blockIdx.x * blockDim.x + threadIdx.x;
    if (i >= n8) return;
    const float4* p = reinterpret_cast<const float4*>(x) + (size_t)i * 2;
    float4 a = p[0], b = p[1];
    uint4 o;
    o.x = packh2(a.x, a.y); o.y = packh2(a.z, a.w);
    o.z = packh2(b.x, b.y); o.w = packh2(b.z, b.w);
    reinterpret_cast<uint4*>(g_X)[i] = o;
}

// in[K][N] fp32  ->  out[N][K] fp16
__global__ void transpose_h_kernel(const float* __restrict__ in, __half* __restrict__ out,
                                   int K, int N) {
    __shared__ float s[32][33];
    int n0 = blockIdx.x * 32, k0 = blockIdx.y * 32;
    int tx = threadIdx.x, ty = threadIdx.y;
#pragma unroll
    for (int i = 0; i < 4; i++)
        s[ty + i * 8][tx] = in[(size_t)(k0 + ty + i * 8) * N + n0 + tx];
    __syncthreads();
#pragma unroll
    for (int i = 0; i < 4; i++) {
        int r = ty + i * 8;
        out[(size_t)(n0 + r) * K + k0 + tx] = __float2half_rn(s[tx][r]);
    }
}

// ---------------------------------------------------------------------------
// Shared GEMM mainloop: C[128x128] = A[128x640] * B[128x640]^T
// 256 threads, 8 warps as 4(m) x 2(n); warp tile 32x64.
// 4-stage cp.async pipeline, one __syncthreads per K-chunk.
// smem: 4 stages x (A 10240B + B 10240B) = 81920 bytes dynamic.
// ---------------------------------------------------------------------------
#define G_STAGE_BYTES 20480
#define G_SMEM_BYTES  (4 * G_STAGE_BYTES)

__device__ __forceinline__ void gemm_mainloop(const __half* __restrict__ Ag,
                                              const __half* __restrict__ Bg,
                                              __half* sm, float acc[2][8][4]) {
    const int tid  = threadIdx.x;
    const int lane = tid & 31, wid = tid >> 5;
    const int wm = wid >> 1, wn = wid & 1;
    const int ldr = (lane & 7) + ((lane >> 3) & 1) * 8;
    const int hib = (lane >> 4) * 16;
    const uint32_t base = smem_u32(sm);

    auto load_stage = [&](int it, int s) {
        const int k0 = it * 32;
        const uint32_t sa = base + (uint32_t)s * G_STAGE_BYTES;
        const uint32_t sbB = sa + 10240;
        for (int i = tid; i < 512; i += 256) {
            int r = i >> 2, c = i & 3;
            uint32_t so = (uint32_t)(r * 40 + c * 8) * 2;
            cp16(sa + so, Ag + (size_t)r * DIM + k0 + c * 8);
            cp16(sbB + so, Bg + (size_t)r * DIM + k0 + c * 8);
        }
        CP_COMMIT();
    };

    load_stage(0, 0);
    load_stage(1, 1);
    load_stage(2, 2);

    for (int it = 0; it < 20; ++it) {
        const int s = it & 3;
        CP_WAIT2();
        __syncthreads();
        if (it + 3 < 20) load_stage(it + 3, (it + 3) & 3);

        const uint32_t sa = base + (uint32_t)s * G_STAGE_BYTES;
        const uint32_t sbB = sa + 10240;
#pragma unroll
        for (int kb = 0; kb < 2; ++kb) {
            uint32_t af[2][4], bf[8][2];
#pragma unroll
            for (int mt = 0; mt < 2; ++mt)
                ldm_x4(af[mt], sa + (uint32_t)((wm * 32 + mt * 16 + ldr) * 40) * 2 + kb * 32 + hib);
#pragma unroll
            for (int np = 0; np < 4; ++np) {
                uint32_t r[4];
                ldm_x4(r, sbB + (uint32_t)((wn * 64 + np * 16 + ldr) * 40) * 2 + kb * 32 + hib);
                bf[np * 2][0] = r[0]; bf[np * 2][1] = r[2];
                bf[np * 2 + 1][0] = r[1]; bf[np * 2 + 1][1] = r[3];
            }
#pragma unroll
            for (int mt = 0; mt < 2; ++mt)
#pragma unroll
                for (int nt = 0; nt < 8; ++nt)
                    mma_16816(acc[mt][nt], af[mt], bf[nt]);
        }
    }
    __syncthreads();   // protect smem reuse by epilogues
}

// ---------------------------------------------------------------------------
// QKV GEMM + scatter epilogue. grid (15, 128), 256 threads.
// ---------------------------------------------------------------------------
__global__ __launch_bounds__(256) void qkv_mma_kernel(const float* __restrict__ bias) {
    extern __shared__ __half dsm[];
    float acc[2][8][4];
#pragma unroll
    for (int i = 0; i < 2; i++)
#pragma unroll
        for (int j = 0; j < 8; j++)
#pragma unroll
            for (int q = 0; q < 4; q++) acc[i][j][q] = 0.f;

    const int bn = blockIdx.x * 128, bm = blockIdx.y * 128;
    gemm_mainloop(g_X + (size_t)bm * DIM, g_Wq + (size_t)bn * DIM, dsm, acc);

    const int tid = threadIdx.x, lane = tid & 31, wid = tid >> 5;
    const int wm = wid >> 1, wn = wid & 1;
    const int gid = lane >> 2, tig = lane & 3;
    const int sel = bn / DIM;                  // 0=Q 1=K 2=V
    const int cc  = bn - sel * DIM;
    const int h0  = cc >> 6;
    const int b   = bm >> 10, n0 = bm & 1023;

    if (sel < 2) {
        __half* dst = sel ? g_K : g_Q;
        const float sc = sel ? 1.f : SCALE_F;
#pragma unroll
        for (int mt = 0; mt < 2; ++mt)
#pragma unroll
            for (int nt = 0; nt < 8; ++nt) {
                int ct = wn * 64 + nt * 8 + 2 * tig;
                int h = h0 + wn, d = ct & 63;
                float b0 = bias[bn + ct], b1 = bias[bn + ct + 1];
                int r0 = wm * 32 + mt * 16 + gid;
                size_t base = (((size_t)b * HEADS + h) * SEQ + n0 + r0) * HDIM + d;
                *(__half2*)(dst + base) =
                    __floats2half2_rn((acc[mt][nt][0] + b0) * sc, (acc[mt][nt][1] + b1) * sc);
                *(__half2*)(dst + base + (size_t)8 * HDIM) =
                    __floats2half2_rn((acc[mt][nt][2] + b0) * sc, (acc[mt][nt][3] + b1) * sc);
            }
    } else {
        // V: transpose through smem to [bh][d][n]
        __half* sT = dsm;   // [128 cols][136]
#pragma unroll
        for (int mt = 0; mt < 2; ++mt)
#pragma unroll
            for (int nt = 0; nt < 8; ++nt) {
                int ct = wn * 64 + nt * 8 + 2 * tig;
                int r0 = wm * 32 + mt * 16 + gid;
                float b0 = bias[bn + ct], b1 = bias[bn + ct + 1];
                sT[ct * 136 + r0]           = __float2half_rn(acc[mt][nt][0] + b0);
                sT[(ct + 1) * 136 + r0]     = __float2half_rn(acc[mt][nt][1] + b1);
                sT[ct * 136 + r0 + 8]       = __float2half_rn(acc[mt][nt][2] + b0);
                sT[(ct + 1) * 136 + r0 + 8] = __float2half_rn(acc[mt][nt][3] + b1);
            }
        __syncthreads();
        int row = tid >> 1, part = tid & 1;           // row = tile col (head-dim)
        int h = h0 + (row >> 6), d = row & 63;
        __half* dst = g_Vt + (((size_t)b * HEADS + h) * HDIM + d) * SEQ + n0 + part * 64;
        const uint4* s4 = (const uint4*)(sT + row * 136 + part * 64);
#pragma unroll
        for (int q = 0; q < 8; ++q) ((uint4*)dst)[q] = s4[q];
    }
}

// ---------------------------------------------------------------------------
// Output projection. grid (5, 128), 256 threads.
// ---------------------------------------------------------------------------
__global__ __launch_bounds__(256) void proj_mma_kernel(const float* __restrict__ bias,
                                                       float* __restrict__ out) {
    extern __shared__ __half dsm[];
    float acc[2][8][4];
#pragma unroll
    for (int i = 0; i < 2; i++)
#pragma unroll
        for (int j = 0; j < 8; j++)
#pragma unroll
            for (int q = 0; q < 4; q++) acc[i][j][q] = 0.f;

    const int bn = blockIdx.x * 128, bm = blockIdx.y * 128;
    gemm_mainloop(g_AO + (size_t)bm * DIM, g_Wo + (size_t)bn * DIM, dsm, acc);

    const int tid = threadIdx.x, lane = tid & 31, wid = tid >> 5;
    const int wm = wid >> 1, wn = wid & 1;
    const int gid = lane >> 2, tig = lane & 3;
#pragma unroll
    for (int mt = 0; mt < 2; ++mt)
#pragma unroll
        for (int nt = 0; nt < 8; ++nt) {
            int ct = wn * 64 + nt * 8 + 2 * tig;
            int m0 = bm + wm * 32 + mt * 16 + gid;
            float b0 = bias[bn + ct], b1 = bias[bn + ct + 1];
            float2 v0 = make_float2(acc[mt][nt][0] + b0, acc[mt][nt][1] + b1);
            float2 v1 = make_float2(acc[mt][nt][2] + b0, acc[mt][nt][3] + b1);
            *(float2*)(out + (size_t)m0 * DIM + bn + ct) = v0;
            *(float2*)(out + (size_t)(m0 + 8) * DIM + bn + ct) = v1;
        }
}

// ---------------------------------------------------------------------------
// Flash attention. grid (160, 8), 256 threads = 8 warps, each warp owns 16
// query rows x all 64 keys -> softmax rows and P stay in registers.
// smem (halves): Q[128][72]=9216, then 3 stages x (K[64][72] + V[64][72]) = 9216 each.
// total = 36864 halves = 73728 bytes dynamic. 3-stage cp.async pipeline.
// ---------------------------------------------------------------------------
#define A_STAGE_H 9216
#define ASM_BYTES (36864 * 2)

__global__ __launch_bounds__(256) void attn_mma_kernel() {
    extern __shared__ __half dsm[];
    const int tid = threadIdx.x, lane = tid & 31, wid = tid >> 5;
    const int gid = lane >> 2, tig = lane & 3;
    const int bh = blockIdx.x, bq = blockIdx.y * 128;
    const int b = bh / HEADS, h = bh - b * HEADS;
    const int ldr = (lane & 7) + ((lane >> 3) & 1) * 8;
    const int hib = (lane >> 4) * 16;

    const __half* Qg = g_Q + ((size_t)bh * SEQ + bq) * HDIM;
    const __half* Kg = g_K + (size_t)bh * SEQ * HDIM;
    const __half* Vg = g_Vt + (size_t)bh * HDIM * SEQ;

    const uint32_t base = smem_u32(dsm);
    const uint32_t kvb  = base + A_STAGE_H * 2;

    auto load_kv = [&](int jt, int s) {
        const __half* Ks = Kg + (size_t)jt * 64 * HDIM;
        const __half* Vs = Vg + jt * 64;
        const uint32_t kS = kvb + (uint32_t)s * (A_STAGE_H * 2);
        const uint32_t vS = kS + 4608 * 2;
        for (int i = tid; i < 512; i += 256) {
            int r = i >> 3, c = i & 7;
            uint32_t so = (uint32_t)(r * 72 + c * 8) * 2;
            cp16(kS + so, Ks + (size_t)r * HDIM + c * 8);
            cp16(vS + so, Vs + (size_t)r * SEQ + c * 8);
        }
        CP_COMMIT();
    };

    // Q tile (resident, padded 72-half rows) + prefetch KV stages 0,1
    for (int i = tid; i < 1024; i += 256) {
        int r = i >> 3, c = i & 7;
        *(uint4*)(dsm + r * 72 + c * 8) = *(const uint4*)(Qg + (size_t)r * HDIM + c * 8);
    }
    load_kv(0, 0);
    load_kv(1, 1);
    __syncthreads();

    uint32_t qf[4][4];
#pragma unroll
    for (int kb = 0; kb < 4; ++kb)
        ldm_x4(qf[kb], base + (uint32_t)((wid * 16 + ldr) * 72) * 2 + kb * 32 + hib);

    float mrow[2] = {-1e30f, -1e30f}, lrow[2] = {0.f, 0.f};
    float oacc[8][4];
#pragma unroll
    for (int j = 0; j < 8; j++)
#pragma unroll
        for (int q = 0; q < 4; q++) oacc[j][q] = 0.f;

    for (int jt = 0; jt < 16; ++jt) {
        const int s = jt % 3;
        CP_WAIT1();
        __syncthreads();
        if (jt + 2 < 16) load_kv(jt + 2, (jt + 2) % 3);

        const uint32_t kS = kvb + (uint32_t)s * (A_STAGE_H * 2);
        const uint32_t vS = kS + 4608 * 2;

        // S = Q K^T  (warp: 16 rows x 64 keys), Q pre-scaled
        float sacc[8][4];
#pragma unroll
        for (int j = 0; j < 8; j++)
#pragma unroll
            for (int q = 0; q < 4; q++) sacc[j][q] = 0.f;
#pragma unroll
        for (int kb = 0; kb < 4; ++kb) {
            uint32_t bf[8][2];
#pragma unroll
            for (int np = 0; np < 4; ++np) {
                uint32_t r[4];
                ldm_x4(r, kS + (uint32_t)((np * 16 + ldr) * 72) * 2 + kb * 32 + hib);
                bf[np * 2][0] = r[0]; bf[np * 2][1] = r[2];
                bf[np * 2 + 1][0] = r[1]; bf[np * 2 + 1][1] = r[3];
            }
#pragma unroll
            for (int nt = 0; nt < 8; ++nt) mma_16816(sacc[nt], qf[kb], bf[nt]);
        }

        // online softmax over 2 rows/thread (quad-replicated)
        float mx0 = -1e30f, mx1 = -1e30f;
#pragma unroll
        for (int nt = 0; nt < 8; ++nt) {
            mx0 = fmaxf(mx0, fmaxf(sacc[nt][0], sacc[nt][1]));
            mx1 = fmaxf(mx1, fmaxf(sacc[nt][2], sacc[nt][3]));
        }
        mx0 = fmaxf(mx0, __shfl_xor_sync(0xffffffffu, mx0, 1));
        mx0 = fmaxf(mx0, __shfl_xor_sync(0xffffffffu, mx0, 2));
        mx1 = fmaxf(mx1, __shfl_xor_sync(0xffffffffu, mx1, 1));
        mx1 = fmaxf(mx1, __shfl_xor_sync(0xffffffffu, mx1, 2));
        float Mn0 = fmaxf(mrow[0], mx0), Mn1 = fmaxf(mrow[1], mx1);
        float c0 = __expf(mrow[0] - Mn0), c1 = __expf(mrow[1] - Mn1);
        mrow[0] = Mn0; mrow[1] = Mn1;
        float s0 = 0.f, s1 = 0.f;
#pragma unroll
        for (int nt = 0; nt < 8; ++nt) {
            float p00 = __expf(sacc[nt][0] - Mn0), p01 = __expf(sacc[nt][1] - Mn0);
            float p10 = __expf(sacc[nt][2] - Mn1), p11 = __expf(sacc[nt][3] - Mn1);
            sacc[nt][0] = p00; sacc[nt][1] = p01; sacc[nt][2] = p10; sacc[nt][3] = p11;
            s0 += p00 + p01; s1 += p10 + p11;
        }
        s0 += __shfl_xor_sync(0xffffffffu, s0, 1);
        s0 += __shfl_xor_sync(0xffffffffu, s0, 2);
        s1 += __shfl_xor_sync(0xffffffffu, s1, 1);
        s1 += __shfl_xor_sync(0xffffffffu, s1, 2);
        lrow[0] = lrow[0] * c0 + s0;
        lrow[1] = lrow[1] * c1 + s1;
#pragma unroll
        for (int nt = 0; nt < 8; ++nt) {
            oacc[nt][0] *= c0; oacc[nt][1] *= c0;
            oacc[nt][2] *= c1; oacc[nt][3] *= c1;
        }

        // O += P V  : P fragments packed straight from registers
#pragma unroll
        for (int kb = 0; kb < 4; ++kb) {
            uint32_t pa[4] = {
                packh2(sacc[2 * kb][0],     sacc[2 * kb][1]),
                packh2(sacc[2 * kb][2],     sacc[2 * kb][3]),
                packh2(sacc[2 * kb + 1][0], sacc[2 * kb + 1][1]),
                packh2(sacc[2 * kb + 1][2], sacc[2 * kb + 1][3]) };
            uint32_t vf[8][2];
#pragma unroll
            for (int np = 0; np < 4; ++np) {
                uint32_t r[4];
                ldm_x4(r, vS + (uint32_t)((np * 16 + ldr) * 72) * 2 + kb * 32 + hib);
                vf[np * 2][0] = r[0]; vf[np * 2][1] = r[2];
                vf[np * 2 + 1][0] = r[1]; vf[np * 2 + 1][1] = r[3];
            }
#pragma unroll
            for (int nt = 0; nt < 8; ++nt) mma_16816(oacc[nt], pa, vf[nt]);
        }
    }

    // epilogue -> AO fp16
    float inv0 = 1.f / lrow[0], inv1 = 1.f / lrow[1];
    size_t m0 = (size_t)b * SEQ + bq + wid * 16 + gid;
#pragma unroll
    for (int nt = 0; nt < 8; ++nt) {
        int col = h * HDIM + nt * 8 + 2 * tig;
        *(__half2*)(g_AO + m0 * DIM + col) =
            __floats2half2_rn(oacc[nt][0] * inv0, oacc[nt][1] * inv0);
        *(__half2*)(g_AO + (m0 + 8) * DIM + col) =
            __floats2half2_rn(oacc[nt][2] * inv1, oacc[nt][3] * inv1);
    }
}

// ---------------------------------------------------------------------------
extern "C" void kernel_launch(void* const* d_in, const int* in_sizes, int n_in,
                              void* d_out, int out_size)
{
    const float* x     = (const float*)d_in[0];
    const float* w_qkv = (const float*)d_in[1];
    const float* b_qkv = (const float*)d_in[2];
    const float* w_out = (const float*)d_in[3];
    const float* b_out = (const float*)d_in[4];
    float* out = (float*)d_out;

    cudaFuncSetAttribute(qkv_mma_kernel,  cudaFuncAttributeMaxDynamicSharedMemorySize, G_SMEM_BYTES);
    cudaFuncSetAttribute(proj_mma_kernel, cudaFuncAttributeMaxDynamicSharedMemorySize, G_SMEM_BYTES);
    cudaFuncSetAttribute(attn_mma_kernel, cudaFuncAttributeMaxDynamicSharedMemorySize, ASM_BYTES);

    __half *wq, *wo;
    cudaGetSymbolAddress((void**)&wq, g_Wq);
    cudaGetSymbolAddress((void**)&wo, g_Wo);

    // converts
    convert_x_kernel<<<(MROWS * DIM / 8 + 255) / 256, 256>>>(x, MROWS * DIM / 8);
    transpose_h_kernel<<<dim3(QKVCOLS / 32, DIM / 32), dim3(32, 8)>>>(w_qkv, wq, DIM, QKVCOLS);
    transpose_h_kernel<<<dim3(DIM / 32, DIM / 32), dim3(32, 8)>>>(w_out, wo, DIM, DIM);
    // QKV GEMM
    qkv_mma_kernel<<<dim3(QKVCOLS / 128, MROWS / 128), 256, G_SMEM_BYTES>>>(b_qkv);
    // attention
    attn_mma_kernel<<<dim3(BH, SEQ / 128), 256, ASM_BYTES>>>();
    // output projection
    proj_mma_kernel<<<dim3(DIM / 128, MROWS / 128), 256, G_SMEM_BYTES>>>(b_out, out);
}